// round 6
// baseline (speedup 1.0000x reference)
#include <cuda_runtime.h>
#include <math_constants.h>

// WeightedChamferDistance: B=4, N=M=8192, D=3.
// out = mean_b( sum_n min_m d2 * w[b,n] ) + mean_b( sum_m min_n d2 )
//
// Pass1 (persistent + work-stealing): 1776 blocks (148 SMs x 12) pull 4096
//       work items off a global counter. Item = 512 points (4/thread) x one
//       256-other chunk, packed-pair fma.rn.f32x2 inner loop. FFMA2 suffers
//       RF-bank rt=3 (3 even + 3 odd distinct regs) -> fma-pipe floor
//       ~36 cyc/iter; work-stealing removes the 15-20% wave tail seen in R5.
// Pass2: min over 32 split-partials, weight fwd direction, block reduce.
// Pass3: final sum of 256 block sums, /BATCH.

#define BATCH   4
#define NPTS    8192
#define TILE    256             // others per chunk (4 KB tile)
#define SPLITS  32              // NPTS / TILE
#define T1      128             // pass1 threads (4 points each)
#define PPB     512             // points per block-item
#define NITEMS  (2 * BATCH * (NPTS / PPB) * SPLITS)   // 4096
#define NBLOCKS (148 * 12)      // persistent grid

__device__ float g_partial[2 * BATCH * NPTS * SPLITS];  // 8 MB
__device__ float g_sums[256];
__device__ unsigned int g_ctr;

__global__ void init_kernel() { g_ctr = 0u; }

__global__ __launch_bounds__(T1, 12)
void chamfer_pass1(const float* __restrict__ src,
                   const float* __restrict__ tgt)
{
    // Tile layout per pair k (8 floats = 32 B):
    //  [0]=-2x0 [1]=-2x1 [2]=-2y0 [3]=-2y1 [4]=-2z0 [5]=-2z1 [6]=o2_0 [7]=o2_1
    __shared__ float s_tile[TILE * 4];
    __shared__ unsigned int s_item;

    unsigned sbase;
    asm("{ .reg .u64 t; cvta.to.shared.u64 t, %1; cvt.u32.u64 %0, t; }"
        : "=r"(sbase) : "l"(s_tile));

    for (;;) {
        __syncthreads();                       // protect s_tile & s_item reuse
        if (threadIdx.x == 0) s_item = atomicAdd(&g_ctr, 1u);
        __syncthreads();
        const unsigned item = s_item;
        if (item >= NITEMS) break;

        const int split = item & (SPLITS - 1);
        const int g     = item >> 5;                     // 0..127 point-group id
        const bool bwd  = g >= (BATCH * (NPTS / PPB));   // >= 64
        const int lg    = g & 63;
        const int b     = lg >> 4;
        const int pg    = lg & 15;

        const float* pts = bwd ? tgt : src;
        const float* oth = bwd ? src : tgt;

        const int pid0 = pg * PPB + threadIdx.x;         // +0,+128,+256,+384

        // Load this thread's four points; duplicate into packed operands
        unsigned long long cx[4], cy[4], cz[4];
        float p2[4];
        #pragma unroll
        for (int k = 0; k < 4; ++k) {
            const float* p = pts + ((size_t)b * NPTS + pid0 + k * T1) * 3;
            const float x = p[0], y = p[1], z = p[2];
            p2[k] = x * x + y * y + z * z;
            asm("mov.b64 %0,{%1,%1};" : "=l"(cx[k]) : "f"(x));
            asm("mov.b64 %0,{%1,%1};" : "=l"(cy[k]) : "f"(y));
            asm("mov.b64 %0,{%1,%1};" : "=l"(cz[k]) : "f"(z));
        }

        // Cooperative tile load + preprocess for this chunk
        const float* obase = oth + ((size_t)b * NPTS + split * TILE) * 3;
        #pragma unroll
        for (int it = 0; it < TILE / T1; ++it) {
            const int idx = it * T1 + threadIdx.x;
            const float* o = obase + (size_t)idx * 3;
            const float ox = o[0], oy = o[1], oz = o[2];
            const float o2 = ox * ox + oy * oy + oz * oz;
            float* bp = s_tile + (idx >> 1) * 8 + (idx & 1);
            bp[0] = -2.0f * ox;
            bp[2] = -2.0f * oy;
            bp[4] = -2.0f * oz;
            bp[6] = o2;
        }
        __syncthreads();

        float m0[4], m1[4];
        #pragma unroll
        for (int k = 0; k < 4; ++k) { m0[k] = CUDART_INF_F; m1[k] = CUDART_INF_F; }

        // Scan: TILE/2 packed pairs; 4 points share each pair of LDS.128
        #pragma unroll 8
        for (int kk = 0; kk < TILE / 2; ++kk) {
            const unsigned a = sbase + kk * 32u;
            unsigned long long txp, typ, tzp, t2p;
            asm("ld.shared.v2.u64 {%0,%1},[%2];" : "=l"(txp), "=l"(typ) : "r"(a));
            asm("ld.shared.v2.u64 {%0,%1},[%2];" : "=l"(tzp), "=l"(t2p) : "r"(a + 16u));
            #pragma unroll
            for (int k = 0; k < 4; ++k) {
                unsigned long long acc;
                asm("fma.rn.f32x2 %0,%1,%2,%3;" : "=l"(acc) : "l"(cx[k]), "l"(txp), "l"(t2p));
                asm("fma.rn.f32x2 %0,%1,%2,%3;" : "=l"(acc) : "l"(cy[k]), "l"(typ), "l"(acc));
                asm("fma.rn.f32x2 %0,%1,%2,%3;" : "=l"(acc) : "l"(cz[k]), "l"(tzp), "l"(acc));
                float lo, hi;
                asm("mov.b64 {%0,%1},%2;" : "=f"(lo), "=f"(hi) : "l"(acc));
                m0[k] = fminf(m0[k], lo);
                m1[k] = fminf(m1[k], hi);
            }
        }

        const int base = ((int)bwd * BATCH + b) * NPTS;
        #pragma unroll
        for (int k = 0; k < 4; ++k) {
            g_partial[(size_t)(base + pid0 + k * T1) * SPLITS + split] =
                p2[k] + fminf(m0[k], m1[k]);
        }
    }
}

__global__ __launch_bounds__(256)
void chamfer_pass2(const float* __restrict__ w)
{
    __shared__ float s_red[256];

    const int q = blockIdx.x * 256 + threadIdx.x;   // 0 .. 65535
    const int bwd = q >> 15;                        // 0 = fwd (weighted)
    const int r   = q & 32767;
    const int b   = r >> 13;
    const int pid = r & (NPTS - 1);

    const float4* pp = (const float4*)(g_partial + (size_t)q * SPLITS);
    float m = CUDART_INF_F;
    #pragma unroll
    for (int i = 0; i < SPLITS / 4; ++i) {
        const float4 v = pp[i];
        m = fminf(m, fminf(fminf(v.x, v.y), fminf(v.z, v.w)));
    }
    if (!bwd) m *= w[(size_t)b * NPTS + pid];

    s_red[threadIdx.x] = m;
    __syncthreads();
    #pragma unroll
    for (int s = 128; s > 0; s >>= 1) {
        if (threadIdx.x < s) s_red[threadIdx.x] += s_red[threadIdx.x + s];
        __syncthreads();
    }
    if (threadIdx.x == 0) g_sums[blockIdx.x] = s_red[0];
}

__global__ void chamfer_pass3(float* __restrict__ out)
{
    __shared__ float s_red[256];
    s_red[threadIdx.x] = g_sums[threadIdx.x];
    __syncthreads();
    #pragma unroll
    for (int s = 128; s > 0; s >>= 1) {
        if (threadIdx.x < s) s_red[threadIdx.x] += s_red[threadIdx.x + s];
        __syncthreads();
    }
    if (threadIdx.x == 0) out[0] = s_red[0] * (1.0f / (float)BATCH);
}

extern "C" void kernel_launch(void* const* d_in, const int* in_sizes, int n_in,
                              void* d_out, int out_size)
{
    const float* src = (const float*)d_in[0];   // [B, N, 3]
    const float* tgt = (const float*)d_in[1];   // [B, M, 3]
    const float* w   = (const float*)d_in[2];   // [B, N]
    float* out = (float*)d_out;

    init_kernel<<<1, 1>>>();
    chamfer_pass1<<<NBLOCKS, T1>>>(src, tgt);
    chamfer_pass2<<<256, 256>>>(w);
    chamfer_pass3<<<1, 256>>>(out);
}

// round 8
// speedup vs baseline: 1.0984x; 1.0984x over previous
#include <cuda_runtime.h>
#include <math_constants.h>

// WeightedChamferDistance: B=4, N=M=8192, D=3.
// out = mean_b( sum_n min_m d2 * w[b,n] ) + mean_b( sum_m min_n d2 )
//
// Pass1: 1024 blocks (single resident wave, no tail); each = 512 points
//        (4/thread, 128 threads) x one 1024-other chunk. Others in shared as
//        packed pairs (-2x,-2y,-2z,|o|^2); fma.rn.f32x2 = 2 others/instr.
//        Next iteration's LDS.128 pair prefetched into registers (R4's ILP
//        win) and FFMA2 stages ordered breadth-first across the 4 points so
//        no consumer issues within FFMA latency of its producer.
// Pass2: min over 8 split-partials, weight fwd direction, block reduce.
// Pass3: final sum of 256 block sums, /BATCH.

#define BATCH   4
#define NPTS    8192
#define TILE    1024            // others per chunk (16 KB tile)
#define SPLITS  8               // NPTS / TILE
#define T1      128             // pass1 threads (4 points each)
#define PPB     512             // points per block

__device__ float g_partial[2 * BATCH * NPTS * SPLITS];  // 2 MB
__device__ float g_sums[256];

__global__ __launch_bounds__(T1, 7)
void chamfer_pass1(const float* __restrict__ src,
                   const float* __restrict__ tgt)
{
    // Tile layout per pair k (8 floats = 32 B):
    //  [0]=-2x0 [1]=-2x1 [2]=-2y0 [3]=-2y1 [4]=-2z0 [5]=-2z1 [6]=o2_0 [7]=o2_1
    __shared__ float s_tile[TILE * 4 + 8];   // +8 floats: prefetch overread pad

    const int bx    = blockIdx.x;
    const int split = bx & (SPLITS - 1);
    const int g     = bx >> 3;                       // 0..127 point-group id
    const bool bwd  = g >= (BATCH * (NPTS / PPB));   // >= 64
    const int lg    = g & 63;
    const int b     = lg >> 4;
    const int pg    = lg & 15;

    const float* pts = bwd ? tgt : src;
    const float* oth = bwd ? src : tgt;

    const int pid0 = pg * PPB + threadIdx.x;         // +0,+128,+256,+384

    // Load this thread's four points; duplicate coords into packed operands
    unsigned long long cx[4], cy[4], cz[4];
    float p2[4];
    #pragma unroll
    for (int k = 0; k < 4; ++k) {
        const float* p = pts + ((size_t)b * NPTS + pid0 + k * T1) * 3;
        const float x = p[0], y = p[1], z = p[2];
        p2[k] = x * x + y * y + z * z;
        asm("mov.b64 %0,{%1,%1};" : "=l"(cx[k]) : "f"(x));
        asm("mov.b64 %0,{%1,%1};" : "=l"(cy[k]) : "f"(y));
        asm("mov.b64 %0,{%1,%1};" : "=l"(cz[k]) : "f"(z));
    }

    unsigned sbase;
    asm("{ .reg .u64 t; cvta.to.shared.u64 t, %1; cvt.u32.u64 %0, t; }"
        : "=r"(sbase) : "l"(s_tile));

    // Cooperative tile load + preprocess for this chunk
    const float* obase = oth + ((size_t)b * NPTS + split * TILE) * 3;
    #pragma unroll
    for (int it = 0; it < TILE / T1; ++it) {
        const int idx = it * T1 + threadIdx.x;
        const float* o = obase + (size_t)idx * 3;
        const float ox = o[0], oy = o[1], oz = o[2];
        const float o2 = ox * ox + oy * oy + oz * oz;
        float* bp = s_tile + (idx >> 1) * 8 + (idx & 1);
        bp[0] = -2.0f * ox;
        bp[2] = -2.0f * oy;
        bp[4] = -2.0f * oz;
        bp[6] = o2;
    }
    __syncthreads();

    float m0[4], m1[4];
    #pragma unroll
    for (int k = 0; k < 4; ++k) { m0[k] = CUDART_INF_F; m1[k] = CUDART_INF_F; }

    // Prefetch iter 0's operands
    unsigned long long txp, typ, tzp, t2p;
    asm("ld.shared.v2.u64 {%0,%1},[%2];" : "=l"(txp), "=l"(typ) : "r"(sbase));
    asm("ld.shared.v2.u64 {%0,%1},[%2];" : "=l"(tzp), "=l"(t2p) : "r"(sbase + 16u));

    // Scan: TILE/2 packed pairs; breadth-first stages across the 4 points
    #pragma unroll 8
    for (int kk = 0; kk < TILE / 2; ++kk) {
        const unsigned a = sbase + kk * 32u + 32u;
        unsigned long long ntx, nty, ntz, nt2;
        asm("ld.shared.v2.u64 {%0,%1},[%2];" : "=l"(ntx), "=l"(nty) : "r"(a));
        asm("ld.shared.v2.u64 {%0,%1},[%2];" : "=l"(ntz), "=l"(nt2) : "r"(a + 16u));

        unsigned long long acc[4];
        #pragma unroll
        for (int k = 0; k < 4; ++k)
            asm("fma.rn.f32x2 %0,%1,%2,%3;" : "=l"(acc[k]) : "l"(cx[k]), "l"(txp), "l"(t2p));
        #pragma unroll
        for (int k = 0; k < 4; ++k)
            asm("fma.rn.f32x2 %0,%1,%2,%3;" : "=l"(acc[k]) : "l"(cy[k]), "l"(typ), "l"(acc[k]));
        #pragma unroll
        for (int k = 0; k < 4; ++k)
            asm("fma.rn.f32x2 %0,%1,%2,%3;" : "=l"(acc[k]) : "l"(cz[k]), "l"(tzp), "l"(acc[k]));
        #pragma unroll
        for (int k = 0; k < 4; ++k) {
            float lo, hi;
            asm("mov.b64 {%0,%1},%2;" : "=f"(lo), "=f"(hi) : "l"(acc[k]));
            m0[k] = fminf(m0[k], lo);
            m1[k] = fminf(m1[k], hi);
        }
        txp = ntx; typ = nty; tzp = ntz; t2p = nt2;
    }

    const int base = ((int)bwd * BATCH + b) * NPTS;
    #pragma unroll
    for (int k = 0; k < 4; ++k) {
        g_partial[(size_t)(base + pid0 + k * T1) * SPLITS + split] =
            p2[k] + fminf(m0[k], m1[k]);
    }
}

__global__ __launch_bounds__(256)
void chamfer_pass2(const float* __restrict__ w)
{
    __shared__ float s_red[256];

    const int q = blockIdx.x * 256 + threadIdx.x;   // 0 .. 65535
    const int bwd = q >> 15;                        // 0 = fwd (weighted)
    const int r   = q & 32767;
    const int b   = r >> 13;
    const int pid = r & (NPTS - 1);

    const float4* pp = (const float4*)(g_partial + (size_t)q * SPLITS);
    const float4 v0 = pp[0];
    const float4 v1 = pp[1];
    float m = fminf(fminf(fminf(v0.x, v0.y), fminf(v0.z, v0.w)),
                    fminf(fminf(v1.x, v1.y), fminf(v1.z, v1.w)));
    if (!bwd) m *= w[(size_t)b * NPTS + pid];

    s_red[threadIdx.x] = m;
    __syncthreads();
    #pragma unroll
    for (int s = 128; s > 0; s >>= 1) {
        if (threadIdx.x < s) s_red[threadIdx.x] += s_red[threadIdx.x + s];
        __syncthreads();
    }
    if (threadIdx.x == 0) g_sums[blockIdx.x] = s_red[0];
}

__global__ void chamfer_pass3(float* __restrict__ out)
{
    __shared__ float s_red[256];
    s_red[threadIdx.x] = g_sums[threadIdx.x];
    __syncthreads();
    #pragma unroll
    for (int s = 128; s > 0; s >>= 1) {
        if (threadIdx.x < s) s_red[threadIdx.x] += s_red[threadIdx.x + s];
        __syncthreads();
    }
    if (threadIdx.x == 0) out[0] = s_red[0] * (1.0f / (float)BATCH);
}

extern "C" void kernel_launch(void* const* d_in, const int* in_sizes, int n_in,
                              void* d_out, int out_size)
{
    const float* src = (const float*)d_in[0];   // [B, N, 3]
    const float* tgt = (const float*)d_in[1];   // [B, M, 3]
    const float* w   = (const float*)d_in[2];   // [B, N]
    float* out = (float*)d_out;

    // 2 dirs * 4 batches * 16 point-groups * 8 splits = 1024 blocks
    chamfer_pass1<<<2 * BATCH * (NPTS / PPB) * SPLITS, T1>>>(src, tgt);
    chamfer_pass2<<<256, 256>>>(w);
    chamfer_pass3<<<1, 256>>>(out);
}